// round 1
// baseline (speedup 1.0000x reference)
#include <cuda_runtime.h>

#define HW 200704
#define C 192
#define NH 6
#define D 32
#define TP 128   // pixels per tile

// ---------------- scratch (device globals; no allocations allowed) ----------
__device__ float g_xn[(size_t)C * HW];
__device__ float g_y [(size_t)C * HW];
__device__ float g_q [(size_t)C * HW];
__device__ float g_k [(size_t)C * HW];
__device__ float g_v [(size_t)C * HW];
__device__ float g_G [NH * D * D];
__device__ float g_qs2[C];
__device__ float g_ks2[C];
__device__ float g_gm[NH * D * D];

// ---------------- zero accumulators (must run every replay) -----------------
__global__ void zero_kernel() {
    for (int i = threadIdx.x; i < NH * D * D; i += 256) g_G[i] = 0.f;
    if (threadIdx.x < C) {
        g_qs2[threadIdx.x] = 0.f;
        g_ks2[threadIdx.x] = 0.f;
    }
}

// ---------------- per-pixel channel LayerNorm -------------------------------
__global__ __launch_bounds__(256) void ln_kernel(const float* __restrict__ x,
                                                 const float* __restrict__ g,
                                                 const float* __restrict__ b) {
    const int p = blockIdx.x * 256 + threadIdx.x;
    float s = 0.f, s2 = 0.f;
    for (int c = 0; c < C; c++) {
        float v = x[(size_t)c * HW + p];
        s += v; s2 += v * v;
    }
    const float mu  = s * (1.f / C);
    const float var = s2 * (1.f / C) - mu * mu;
    const float rstd = rsqrtf(var + 1e-5f);
    for (int c = 0; c < C; c++) {
        float v = x[(size_t)c * HW + p];
        g_xn[(size_t)c * HW + p] = (v - mu) * rstd * __ldg(&g[c]) + __ldg(&b[c]);
    }
}

// ---------------- generic fp32 GEMM: out[o][p] = sum_c W[o][c] * in[c][p] ----
// 512 threads, 6x8 register tile per thread, full 192xK input tile in smem,
// weights streamed through smem in 16-column chunks.
__global__ __launch_bounds__(512, 1) void gemm_kernel(const float* __restrict__ in,
                                                      const float* __restrict__ W,
                                                      const float* __restrict__ bias,
                                                      float* __restrict__ out) {
    extern __shared__ float sm[];
    float* in_s = sm;          // [C][TP]
    float* w_s  = sm + C * TP; // [16][C]  (layout [ci][o])
    const int tid = threadIdx.x;
    const int p0  = blockIdx.x * TP;

    for (int i = tid; i < C * TP; i += 512) {
        int c = i >> 7, pp = i & 127;
        in_s[i] = in[(size_t)c * HW + p0 + pp];
    }

    const int tx = tid & 15;   // pixel group: pixels tx*8 .. tx*8+7
    const int ty = tid >> 4;   // row group (0..31): rows ty*6 .. ty*6+5

    float acc[6][8];
#pragma unroll
    for (int i = 0; i < 6; i++) {
        float bv = bias ? __ldg(&bias[ty * 6 + i]) : 0.f;
#pragma unroll
        for (int j = 0; j < 8; j++) acc[i][j] = bv;
    }

    for (int cc = 0; cc < C; cc += 16) {
        __syncthreads();
        for (int i = tid; i < 16 * C; i += 512) {
            int o = i >> 4, ci = i & 15;
            w_s[ci * C + o] = W[o * C + cc + ci];
        }
        __syncthreads();
#pragma unroll 4
        for (int ci = 0; ci < 16; ci++) {
            const float4* xp = reinterpret_cast<const float4*>(in_s + (cc + ci) * TP) + tx * 2;
            float4 xa = xp[0], xb = xp[1];
            const float2* wp = reinterpret_cast<const float2*>(w_s + ci * C) + ty * 3;
            float2 w0 = wp[0], w1 = wp[1], w2 = wp[2];
            float xr[8] = {xa.x, xa.y, xa.z, xa.w, xb.x, xb.y, xb.z, xb.w};
            float wr[6] = {w0.x, w0.y, w1.x, w1.y, w2.x, w2.y};
#pragma unroll
            for (int i = 0; i < 6; i++)
#pragma unroll
                for (int j = 0; j < 8; j++)
                    acc[i][j] += wr[i] * xr[j];
        }
    }

#pragma unroll
    for (int i = 0; i < 6; i++) {
        float* op = out + (size_t)(ty * 6 + i) * HW + p0 + tx * 8;
        reinterpret_cast<float4*>(op)[0] =
            make_float4(acc[i][0], acc[i][1], acc[i][2], acc[i][3]);
        reinterpret_cast<float4*>(op)[1] =
            make_float4(acc[i][4], acc[i][5], acc[i][6], acc[i][7]);
    }
}

// ---------------- Gram + squared-norm reduction ------------------------------
// 192 threads = 6 warps; warp w == head w, lane-thread dd owns G row dd.
__global__ __launch_bounds__(192, 1) void greduce_kernel(const float* __restrict__ q,
                                                         const float* __restrict__ k) {
    extern __shared__ float sm[];
    float* qs_ = sm;             // [C][129] padded
    float* ks_ = sm + C * 129;
    const int tid = threadIdx.x;
    const int p0  = blockIdx.x * TP;

    for (int i = tid; i < C * TP; i += 192) {
        int c = i >> 7, pp = i & 127;
        qs_[c * 129 + pp] = q[(size_t)c * HW + p0 + pp];
        ks_[c * 129 + pp] = k[(size_t)c * HW + p0 + pp];
    }
    __syncthreads();

    const int dd = tid;
    const int h  = dd >> 5;
    float acc[32];
#pragma unroll
    for (int e = 0; e < 32; e++) acc[e] = 0.f;
    float sq = 0.f, sk = 0.f;
    const float* krow = ks_ + (h * 32) * 129;

#pragma unroll 2
    for (int p = 0; p < TP; p++) {
        float qv = qs_[dd * 129 + p];
        float kv = ks_[dd * 129 + p];
        sq += qv * qv;
        sk += kv * kv;
#pragma unroll
        for (int e = 0; e < 32; e++) acc[e] += qv * krow[e * 129 + p];
    }
#pragma unroll
    for (int e = 0; e < 32; e++) atomicAdd(&g_G[dd * 32 + e], acc[e]);
    atomicAdd(&g_qs2[dd], sq);
    atomicAdd(&g_ks2[dd], sk);
}

// ---------------- attn normalize + mn mix + gating  (one tiny block) --------
__global__ void gmk_kernel(const float* __restrict__ mn_w,
                           const float* __restrict__ gating) {
    __shared__ float attn[NH * D * D];
    __shared__ float rq[C], rk[C];
    const int tid = threadIdx.x;
    if (tid < C) {
        rq[tid] = 1.f / fmaxf(sqrtf(g_qs2[tid]), 1e-12f);
        rk[tid] = 1.f / fmaxf(sqrtf(g_ks2[tid]), 1e-12f);
    }
    __syncthreads();
    for (int i = tid; i < NH * D * D; i += 256) {
        int dd = i >> 5, e = i & 31, h = dd >> 5;
        attn[i] = g_G[i] * rq[dd] * rk[h * 32 + e];
    }
    __syncthreads();
    for (int i = tid; i < NH * D * D; i += 256) {
        int dd = i >> 5, e2 = i & 31, h = dd >> 5;
        float s1 = 0.f, s2 = 0.f;
        for (int e = 0; e < 32; e++) {
            float a = attn[dd * 32 + e];
            s1 += a * __ldg(&mn_w[e2 * 32 + e]);
            s2 += a * __ldg(&mn_w[(32 + e2) * 32 + e]);
        }
        g_gm[i] = __ldg(&gating[h]) * s1 + __ldg(&gating[NH + h]) * s2;
    }
}

// ---------------- final: mi = gm@cond, t = mi*v, softmax_d, proj, +x --------
__global__ __launch_bounds__(512, 1) void final_kernel(const float* __restrict__ cond,
                                                       const float* __restrict__ x,
                                                       const float* __restrict__ projw,
                                                       const float* __restrict__ v,
                                                       float* __restrict__ out) {
    extern __shared__ float sm[];
    float* buf  = sm;                    // [C][TP] : cond -> v -> t -> softmax
    float* gm_s = sm + C * TP;           // 6144
    float* w_s  = gm_s + NH * D * D;     // [16][C]
    const int tid = threadIdx.x;
    const int p0  = blockIdx.x * TP;
    const int tx  = tid & 15, ty = tid >> 4;

    for (int i = tid; i < NH * D * D; i += 512) gm_s[i] = g_gm[i];
    for (int i = tid; i < C * TP; i += 512) {
        int c = i >> 7, pp = i & 127;
        buf[i] = cond[(size_t)c * HW + p0 + pp];
    }
    __syncthreads();

    // mi[row][px] = sum_e gm[row][e] * cond[head(row)*32+e][px]
    float t[6][8];
#pragma unroll
    for (int i = 0; i < 6; i++) {
        const int row = ty * 6 + i;
        const int h   = row >> 5;
#pragma unroll
        for (int j = 0; j < 8; j++) t[i][j] = 0.f;
#pragma unroll 4
        for (int e = 0; e < 32; e++) {
            float gv = gm_s[row * 32 + e];
            const float4* cp = reinterpret_cast<const float4*>(buf + (h * 32 + e) * TP) + tx * 2;
            float4 ca = cp[0], cb = cp[1];
            t[i][0] += gv * ca.x; t[i][1] += gv * ca.y;
            t[i][2] += gv * ca.z; t[i][3] += gv * ca.w;
            t[i][4] += gv * cb.x; t[i][5] += gv * cb.y;
            t[i][6] += gv * cb.z; t[i][7] += gv * cb.w;
        }
    }
    __syncthreads();

    // overwrite buf with v tile
    for (int i = tid; i < C * TP; i += 512) {
        int c = i >> 7, pp = i & 127;
        buf[i] = v[(size_t)c * HW + p0 + pp];
    }
    __syncthreads();

    // t = mi * v  (elementwise, exclusive slot ownership)
#pragma unroll
    for (int i = 0; i < 6; i++) {
        const int row = ty * 6 + i;
#pragma unroll
        for (int j = 0; j < 8; j++) {
            int idx = row * TP + tx * 8 + j;
            buf[idx] = t[i][j] * buf[idx];
        }
    }
    __syncthreads();

    // softmax over d (32 rows per head) per (head, pixel)
    for (int task = tid; task < NH * TP; task += 512) {
        int h = task >> 7, p = task & 127;
        float* col = buf + (h * 32) * TP + p;
        float m = -1e30f;
#pragma unroll
        for (int d = 0; d < 32; d++) m = fmaxf(m, col[d * TP]);
        float s = 0.f;
#pragma unroll
        for (int d = 0; d < 32; d++) {
            float e = expf(col[d * TP] - m);
            col[d * TP] = e;
            s += e;
        }
        float r = 1.f / s;
#pragma unroll
        for (int d = 0; d < 32; d++) col[d * TP] *= r;
    }

    // proj GEMM + residual
    float acc[6][8];
#pragma unroll
    for (int i = 0; i < 6; i++)
#pragma unroll
        for (int j = 0; j < 8; j++) acc[i][j] = 0.f;

    for (int cc = 0; cc < C; cc += 16) {
        __syncthreads();
        for (int i = tid; i < 16 * C; i += 512) {
            int o = i >> 4, ci = i & 15;
            w_s[ci * C + o] = projw[o * C + cc + ci];
        }
        __syncthreads();
#pragma unroll 4
        for (int ci = 0; ci < 16; ci++) {
            const float4* xp = reinterpret_cast<const float4*>(buf + (cc + ci) * TP) + tx * 2;
            float4 xa = xp[0], xb = xp[1];
            const float2* wp = reinterpret_cast<const float2*>(w_s + ci * C) + ty * 3;
            float2 w0 = wp[0], w1 = wp[1], w2 = wp[2];
            float xr[8] = {xa.x, xa.y, xa.z, xa.w, xb.x, xb.y, xb.z, xb.w};
            float wr[6] = {w0.x, w0.y, w1.x, w1.y, w2.x, w2.y};
#pragma unroll
            for (int i = 0; i < 6; i++)
#pragma unroll
                for (int j = 0; j < 8; j++)
                    acc[i][j] += wr[i] * xr[j];
        }
    }

#pragma unroll
    for (int i = 0; i < 6; i++) {
        const int o = ty * 6 + i;
        const float* xp = x + (size_t)o * HW + p0 + tx * 8;
        float4 xa = reinterpret_cast<const float4*>(xp)[0];
        float4 xb = reinterpret_cast<const float4*>(xp)[1];
        float* op = out + (size_t)o * HW + p0 + tx * 8;
        reinterpret_cast<float4*>(op)[0] = make_float4(
            acc[i][0] + xa.x, acc[i][1] + xa.y, acc[i][2] + xa.z, acc[i][3] + xa.w);
        reinterpret_cast<float4*>(op)[1] = make_float4(
            acc[i][4] + xb.x, acc[i][5] + xb.y, acc[i][6] + xb.z, acc[i][7] + xb.w);
    }
}

// ---------------- launch -----------------------------------------------------
extern "C" void kernel_launch(void* const* d_in, const int* in_sizes, int n_in,
                              void* d_out, int out_size) {
    const float* x      = (const float*)d_in[0];
    const float* cond   = (const float*)d_in[1];
    const float* ln_g   = (const float*)d_in[2];
    const float* ln_b   = (const float*)d_in[3];
    const float* pre_w  = (const float*)d_in[4];
    const float* pre_b  = (const float*)d_in[5];
    const float* qkv_w  = (const float*)d_in[6];
    const float* mn_w   = (const float*)d_in[7];
    const float* gating = (const float*)d_in[8];
    const float* proj_w = (const float*)d_in[9];
    float* out = (float*)d_out;

    float *p_xn, *p_y, *p_q, *p_k, *p_v;
    cudaGetSymbolAddress((void**)&p_xn, g_xn);
    cudaGetSymbolAddress((void**)&p_y,  g_y);
    cudaGetSymbolAddress((void**)&p_q,  g_q);
    cudaGetSymbolAddress((void**)&p_k,  g_k);
    cudaGetSymbolAddress((void**)&p_v,  g_v);

    const int SM_GEMM = (C * TP + 16 * C) * 4;              // 110592 B
    const int SM_GR   = (2 * C * 129) * 4;                  // 198144 B
    const int SM_FIN  = (C * TP + NH * D * D + 16 * C) * 4; // 135168 B
    cudaFuncSetAttribute(gemm_kernel,    cudaFuncAttributeMaxDynamicSharedMemorySize, SM_GEMM);
    cudaFuncSetAttribute(greduce_kernel, cudaFuncAttributeMaxDynamicSharedMemorySize, SM_GR);
    cudaFuncSetAttribute(final_kernel,   cudaFuncAttributeMaxDynamicSharedMemorySize, SM_FIN);

    zero_kernel<<<1, 256>>>();
    ln_kernel<<<HW / 256, 256>>>(x, ln_g, ln_b);
    gemm_kernel<<<HW / TP, 512, SM_GEMM>>>(p_xn, pre_w, pre_b, p_y);
    gemm_kernel<<<HW / TP, 512, SM_GEMM>>>(p_y, qkv_w,             nullptr, p_q);
    gemm_kernel<<<HW / TP, 512, SM_GEMM>>>(p_y, qkv_w + C * C,     nullptr, p_k);
    gemm_kernel<<<HW / TP, 512, SM_GEMM>>>(p_y, qkv_w + 2 * C * C, nullptr, p_v);
    greduce_kernel<<<HW / TP, 192, SM_GR>>>(p_q, p_k);
    gmk_kernel<<<1, 256>>>(mn_w, gating);
    final_kernel<<<HW / TP, 512, SM_FIN>>>(cond, x, proj_w, p_v, out);
}

// round 3
// speedup vs baseline: 2.5073x; 2.5073x over previous
#include <cuda_runtime.h>
#include <cuda_bf16.h>

#define HW 200704
#define C 192
#define TP 128
#define NH 6
#define D 32
#define AS 136       // fp32 input-tile row stride (bank-conflict-free mma A loads)
#define WS 200       // fp32 weight-chunk row stride (conflict-free B loads)
#define QS 136       // bf16 q/k tile row stride

// ---------------- scratch (device globals; no allocations allowed) ----------
__device__ float g_y[(size_t)C * HW];
__device__ float g_v[(size_t)C * HW];
__device__ float g_G[NH * D * D];
__device__ float g_qs2[C];
__device__ float g_ks2[C];
__device__ float g_gm[NH * D * D];

// ---------------- mma helpers ------------------------------------------------
__device__ __forceinline__ unsigned f2tf(float f) {
    unsigned u;
    asm("cvt.rna.tf32.f32 %0, %1;" : "=r"(u) : "f"(f));
    return u;
}

__device__ __forceinline__ void mma_tf32(float d[4], const unsigned a[4],
                                         unsigned b0, unsigned b1) {
    asm volatile(
        "mma.sync.aligned.m16n8k8.row.col.f32.tf32.tf32.f32 "
        "{%0,%1,%2,%3},{%4,%5,%6,%7},{%8,%9},{%0,%1,%2,%3};\n"
        : "+f"(d[0]), "+f"(d[1]), "+f"(d[2]), "+f"(d[3])
        : "r"(a[0]), "r"(a[1]), "r"(a[2]), "r"(a[3]), "r"(b0), "r"(b1));
}

__device__ __forceinline__ void mma_bf16(float d[4], const unsigned a[4],
                                         unsigned b0, unsigned b1) {
    asm volatile(
        "mma.sync.aligned.m16n8k16.row.col.f32.bf16.bf16.f32 "
        "{%0,%1,%2,%3},{%4,%5,%6,%7},{%8,%9},{%0,%1,%2,%3};\n"
        : "+f"(d[0]), "+f"(d[1]), "+f"(d[2]), "+f"(d[3])
        : "r"(a[0]), "r"(a[1]), "r"(a[2]), "r"(a[3]), "r"(b0), "r"(b1));
}

// GEMM over one [192ch x 128px] fp32 smem tile (stride AS) with W[192out x 192in]
// streamed through w_s in 16-deep chunks. acc[mt][nt][r] per-thread fragment.
// Warp grid 2(M)x4(N): warp tile 64px x 48out. All 256 threads must call this.
__device__ __forceinline__ void gemm_tile(const float* in_s, float* w_s,
                                          const float* __restrict__ W,
                                          float acc[4][6][4], int tid) {
    const int lane = tid & 31, warp = tid >> 5;
    const int gid = lane >> 2, tg = lane & 3;
    const int mb = (warp & 1) * 64, nb = (warp >> 1) * 48;
    for (int cc = 0; cc < C; cc += 16) {
        __syncthreads();
        for (int i = tid; i < 16 * C; i += 256) {
            int ci = i & 15, o = i >> 4;
            w_s[ci * WS + o] = W[o * C + cc + ci];
        }
        __syncthreads();
#pragma unroll
        for (int kl = 0; kl < 16; kl += 8) {
            unsigned a[4][4];
#pragma unroll
            for (int mt = 0; mt < 4; mt++) {
                const float* ab = in_s + (cc + kl + tg) * AS + mb + mt * 16 + gid;
                a[mt][0] = f2tf(ab[0]);
                a[mt][1] = f2tf(ab[8]);
                a[mt][2] = f2tf(ab[4 * AS]);
                a[mt][3] = f2tf(ab[4 * AS + 8]);
            }
#pragma unroll
            for (int nt = 0; nt < 6; nt++) {
                const float* wb = w_s + (kl + tg) * WS + nb + nt * 8 + gid;
                unsigned b0 = f2tf(wb[0]);
                unsigned b1 = f2tf(wb[4 * WS]);
#pragma unroll
                for (int mt = 0; mt < 4; mt++) mma_tf32(acc[mt][nt], a[mt], b0, b1);
            }
        }
    }
}

// ---------------- zero accumulators (runs every replay) ----------------------
__global__ void zero_kernel() {
    for (int i = threadIdx.x; i < NH * D * D; i += 256) g_G[i] = 0.f;
    if (threadIdx.x < C) {
        g_qs2[threadIdx.x] = 0.f;
        g_ks2[threadIdx.x] = 0.f;
    }
}

// ---------------- k1: LayerNorm (fused) + pre 1x1 conv -----------------------
__global__ __launch_bounds__(256, 1) void k1_ln_pre(const float* __restrict__ x,
                                                    const float* __restrict__ g,
                                                    const float* __restrict__ bta,
                                                    const float* __restrict__ pre_w,
                                                    const float* __restrict__ pre_b,
                                                    float* __restrict__ y) {
    extern __shared__ float sm[];
    float* in_s = sm;                  // [C][AS]
    float* w_s  = in_s + C * AS;       // [16][WS]
    float* red  = w_s + 16 * WS;       // 256
    float* red2 = red + 256;           // 256
    float* mu_s = red2 + 256;          // 128
    float* rs_s = mu_s + 128;          // 128
    const int tid = threadIdx.x;
    const int p0  = blockIdx.x * TP;

    for (int i = tid; i < C * (TP / 4); i += 256) {
        int c = i >> 5, p4 = i & 31;
        ((float4*)(in_s + c * AS))[p4] = ((const float4*)(x + (size_t)c * HW + p0))[p4];
    }
    __syncthreads();
    {
        int px = tid & 127, half = tid >> 7;
        float s = 0.f, s2 = 0.f;
        for (int c = half * 96; c < half * 96 + 96; c++) {
            float v = in_s[c * AS + px];
            s += v; s2 += v * v;
        }
        red[tid] = s; red2[tid] = s2;
    }
    __syncthreads();
    if (tid < 128) {
        float s = red[tid] + red[tid + 128];
        float s2 = red2[tid] + red2[tid + 128];
        float mu = s * (1.f / C);
        float var = s2 * (1.f / C) - mu * mu;
        mu_s[tid] = mu;
        rs_s[tid] = rsqrtf(var + 1e-5f);
    }
    __syncthreads();
    for (int i = tid; i < C * TP; i += 256) {
        int c = i >> 7, p = i & 127;
        in_s[c * AS + p] =
            (in_s[c * AS + p] - mu_s[p]) * rs_s[p] * __ldg(&g[c]) + __ldg(&bta[c]);
    }

    const int lane = tid & 31, warp = tid >> 5;
    const int gid = lane >> 2, tg = lane & 3;
    const int mb = (warp & 1) * 64, nb = (warp >> 1) * 48;
    float acc[4][6][4];
#pragma unroll
    for (int nt = 0; nt < 6; nt++) {
        float b0 = __ldg(&pre_b[nb + nt * 8 + 2 * tg]);
        float b1 = __ldg(&pre_b[nb + nt * 8 + 2 * tg + 1]);
#pragma unroll
        for (int mt = 0; mt < 4; mt++) {
            acc[mt][nt][0] = b0; acc[mt][nt][1] = b1;
            acc[mt][nt][2] = b0; acc[mt][nt][3] = b1;
        }
    }
    gemm_tile(in_s, w_s, pre_w, acc, tid);
#pragma unroll
    for (int mt = 0; mt < 4; mt++)
#pragma unroll
        for (int nt = 0; nt < 6; nt++) {
            int o = nb + nt * 8 + 2 * tg;
            size_t i00 = (size_t)o * HW + p0 + mb + mt * 16 + gid;
            y[i00]          = acc[mt][nt][0];
            y[i00 + HW]     = acc[mt][nt][1];
            y[i00 + 8]      = acc[mt][nt][2];
            y[i00 + HW + 8] = acc[mt][nt][3];
        }
}

// ---------------- k2: qkv GEMMs + in-tile Gram/norm reduction ----------------
__global__ __launch_bounds__(256, 1) void k2_qkv(const float* __restrict__ y,
                                                 const float* __restrict__ qkv_w,
                                                 float* __restrict__ v) {
    extern __shared__ float sm[];
    float* y_s = sm;               // [C][AS]
    float* w_s = y_s + C * AS;     // [16][WS]
    __nv_bfloat16* q_s = (__nv_bfloat16*)(w_s + 16 * WS);  // [C][QS] bf16
    __nv_bfloat16* k_s = q_s + C * QS;                     // [C][QS] bf16
    const int tid = threadIdx.x;
    const int p0  = blockIdx.x * TP;
    const int lane = tid & 31, warp = tid >> 5;
    const int gid = lane >> 2, tg = lane & 3;
    const int mb = (warp & 1) * 64, nb = (warp >> 1) * 48;

    for (int i = tid; i < C * (TP / 4); i += 256) {
        int c = i >> 5, p4 = i & 31;
        ((float4*)(y_s + c * AS))[p4] = ((const float4*)(y + (size_t)c * HW + p0))[p4];
    }

    for (int ph = 0; ph < 3; ph++) {
        float acc[4][6][4];
#pragma unroll
        for (int mt = 0; mt < 4; mt++)
#pragma unroll
            for (int nt = 0; nt < 6; nt++)
#pragma unroll
                for (int r = 0; r < 4; r++) acc[mt][nt][r] = 0.f;
        gemm_tile(y_s, w_s, qkv_w + ph * C * C, acc, tid);
        if (ph < 2) {
            __nv_bfloat16* dst = ph ? k_s : q_s;
#pragma unroll
            for (int mt = 0; mt < 4; mt++)
#pragma unroll
                for (int nt = 0; nt < 6; nt++) {
                    int o = nb + nt * 8 + 2 * tg;
                    int p = mb + mt * 16 + gid;
                    dst[o * QS + p]           = __float2bfloat16(acc[mt][nt][0]);
                    dst[(o + 1) * QS + p]     = __float2bfloat16(acc[mt][nt][1]);
                    dst[o * QS + p + 8]       = __float2bfloat16(acc[mt][nt][2]);
                    dst[(o + 1) * QS + p + 8] = __float2bfloat16(acc[mt][nt][3]);
                }
        } else {
#pragma unroll
            for (int mt = 0; mt < 4; mt++)
#pragma unroll
                for (int nt = 0; nt < 6; nt++) {
                    int o = nb + nt * 8 + 2 * tg;
                    size_t i00 = (size_t)o * HW + p0 + mb + mt * 16 + gid;
                    v[i00]          = acc[mt][nt][0];
                    v[i00 + HW]     = acc[mt][nt][1];
                    v[i00 + 8]      = acc[mt][nt][2];
                    v[i00 + HW + 8] = acc[mt][nt][3];
                }
        }
    }
    __syncthreads();

    // Gram per head via bf16 mma over K = 128 pixels (warp w == head w)
    if (warp < 6) {
        const int h = warp;
        float dG[2][4][4];
#pragma unroll
        for (int mt = 0; mt < 2; mt++)
#pragma unroll
            for (int nt = 0; nt < 4; nt++)
#pragma unroll
                for (int r = 0; r < 4; r++) dG[mt][nt][r] = 0.f;
        for (int kc = 0; kc < TP; kc += 16) {
            unsigned a[2][4];
#pragma unroll
            for (int mt = 0; mt < 2; mt++) {
                const __nv_bfloat16* ab = q_s + (h * 32 + mt * 16 + gid) * QS + kc + 2 * tg;
                a[mt][0] = *(const unsigned*)(ab);
                a[mt][1] = *(const unsigned*)(ab + 8 * QS);
                a[mt][2] = *(const unsigned*)(ab + 8);
                a[mt][3] = *(const unsigned*)(ab + 8 * QS + 8);
            }
#pragma unroll
            for (int nt = 0; nt < 4; nt++) {
                const __nv_bfloat16* bb = k_s + (h * 32 + nt * 8 + gid) * QS + kc + 2 * tg;
                unsigned b0 = *(const unsigned*)(bb);
                unsigned b1 = *(const unsigned*)(bb + 8);
#pragma unroll
                for (int mt = 0; mt < 2; mt++) mma_bf16(dG[mt][nt], a[mt], b0, b1);
            }
        }
#pragma unroll
        for (int mt = 0; mt < 2; mt++)
#pragma unroll
            for (int nt = 0; nt < 4; nt++) {
                int r0 = h * 32 + mt * 16 + gid, c0 = nt * 8 + 2 * tg;
                atomicAdd(&g_G[r0 * 32 + c0],           dG[mt][nt][0]);
                atomicAdd(&g_G[r0 * 32 + c0 + 1],       dG[mt][nt][1]);
                atomicAdd(&g_G[(r0 + 8) * 32 + c0],     dG[mt][nt][2]);
                atomicAdd(&g_G[(r0 + 8) * 32 + c0 + 1], dG[mt][nt][3]);
            }
    }
    // squared norms (consistent with the bf16 values used in the Gram)
    for (int i = tid; i < 2 * C; i += 256) {
        const __nv_bfloat16* arr = (i < C) ? q_s : k_s;
        int row = (i < C) ? i : i - C;
        float s = 0.f;
        for (int p = 0; p < TP; p++) {
            float vv = __bfloat162float(arr[row * QS + p]);
            s += vv * vv;
        }
        atomicAdd((i < C) ? &g_qs2[row] : &g_ks2[row], s);
    }
}

// ---------------- attn normalize + mn mix + gating (tiny) --------------------
__global__ void gmk_kernel(const float* __restrict__ mn_w,
                           const float* __restrict__ gating) {
    __shared__ float attn[NH * D * D];
    __shared__ float rq[C], rk[C];
    const int tid = threadIdx.x;
    if (tid < C) {
        rq[tid] = 1.f / fmaxf(sqrtf(g_qs2[tid]), 1e-12f);
        rk[tid] = 1.f / fmaxf(sqrtf(g_ks2[tid]), 1e-12f);
    }
    __syncthreads();
    for (int i = tid; i < NH * D * D; i += 256) {
        int dd = i >> 5, e = i & 31, h = dd >> 5;
        attn[i] = g_G[i] * rq[dd] * rk[h * 32 + e];
    }
    __syncthreads();
    for (int i = tid; i < NH * D * D; i += 256) {
        int dd = i >> 5, e2 = i & 31, h = dd >> 5;
        float s1 = 0.f, s2 = 0.f;
        for (int e = 0; e < 32; e++) {
            float a = attn[dd * 32 + e];
            s1 += a * __ldg(&mn_w[e2 * 32 + e]);
            s2 += a * __ldg(&mn_w[(32 + e2) * 32 + e]);
        }
        g_gm[i] = __ldg(&gating[h]) * s1 + __ldg(&gating[NH + h]) * s2;
    }
}

// ---------------- k4: mi = gm@cond, t = mi*v, softmax_d, proj(mma), +x -------
__global__ __launch_bounds__(256, 1) void k4_final(const float* __restrict__ cond,
                                                   const float* __restrict__ x,
                                                   const float* __restrict__ projw,
                                                   const float* __restrict__ v,
                                                   float* __restrict__ out) {
    extern __shared__ float sm[];
    float* buf  = sm;               // [C][AS] : cond -> v -> t -> softmax
    float* w_s  = buf + C * AS;     // [16][WS]
    float* gm_s = w_s + 16 * WS;    // [192][32]
    const int tid = threadIdx.x;
    const int p0  = blockIdx.x * TP;
    const int tx = tid & 15, ty = tid >> 4;

    for (int i = tid; i < NH * D * D; i += 256) gm_s[i] = g_gm[i];
    for (int i = tid; i < C * (TP / 4); i += 256) {
        int c = i >> 5, p4 = i & 31;
        ((float4*)(buf + c * AS))[p4] = ((const float4*)(cond + (size_t)c * HW + p0))[p4];
    }
    __syncthreads();

    // mi[row][px] = sum_e gm[row][e] * cond[head(row)*32+e][px]
    float t[12][8];
#pragma unroll
    for (int i = 0; i < 12; i++) {
        const int row = ty * 12 + i;
        const int h = row >> 5;
#pragma unroll
        for (int j = 0; j < 8; j++) t[i][j] = 0.f;
#pragma unroll 4
        for (int e = 0; e < 32; e++) {
            float gv = gm_s[row * 32 + e];
            const float4* cp = (const float4*)(buf + (h * 32 + e) * AS + tx * 8);
            float4 ca = cp[0], cb = cp[1];
            t[i][0] += gv * ca.x; t[i][1] += gv * ca.y;
            t[i][2] += gv * ca.z; t[i][3] += gv * ca.w;
            t[i][4] += gv * cb.x; t[i][5] += gv * cb.y;
            t[i][6] += gv * cb.z; t[i][7] += gv * cb.w;
        }
    }
    __syncthreads();
    for (int i = tid; i < C * (TP / 4); i += 256) {
        int c = i >> 5, p4 = i & 31;
        ((float4*)(buf + c * AS))[p4] = ((const float4*)(v + (size_t)c * HW + p0))[p4];
    }
    __syncthreads();
#pragma unroll
    for (int i = 0; i < 12; i++) {
        const int row = ty * 12 + i;
#pragma unroll
        for (int j = 0; j < 8; j++) {
            int idx = row * AS + tx * 8 + j;
            buf[idx] = t[i][j] * buf[idx];
        }
    }
    __syncthreads();

    // softmax over head-dim (32 rows) per (head, pixel)
    for (int task = tid; task < NH * TP; task += 256) {
        int h = task >> 7, p = task & 127;
        float* colp = buf + (h * 32) * AS + p;
        float m = -1e30f;
#pragma unroll
        for (int d = 0; d < 32; d++) m = fmaxf(m, colp[d * AS]);
        float s = 0.f;
#pragma unroll
        for (int d = 0; d < 32; d++) {
            float e = __expf(colp[d * AS] - m);
            colp[d * AS] = e;
            s += e;
        }
        float r = 1.f / s;
#pragma unroll
        for (int d = 0; d < 32; d++) colp[d * AS] *= r;
    }

    // proj GEMM + residual
    const int lane = tid & 31, warp = tid >> 5;
    const int gid = lane >> 2, tg = lane & 3;
    const int mb = (warp & 1) * 64, nb = (warp >> 1) * 48;
    float acc[4][6][4];
#pragma unroll
    for (int mt = 0; mt < 4; mt++)
#pragma unroll
        for (int nt = 0; nt < 6; nt++)
#pragma unroll
            for (int r = 0; r < 4; r++) acc[mt][nt][r] = 0.f;
    gemm_tile(buf, w_s, projw, acc, tid);
#pragma unroll
    for (int mt = 0; mt < 4; mt++)
#pragma unroll
        for (int nt = 0; nt < 6; nt++) {
            int o = nb + nt * 8 + 2 * tg;
            size_t i00 = (size_t)o * HW + p0 + mb + mt * 16 + gid;
            out[i00]          = acc[mt][nt][0] + __ldg(&x[i00]);
            out[i00 + HW]     = acc[mt][nt][1] + __ldg(&x[i00 + HW]);
            out[i00 + 8]      = acc[mt][nt][2] + __ldg(&x[i00 + 8]);
            out[i00 + HW + 8] = acc[mt][nt][3] + __ldg(&x[i00 + HW + 8]);
        }
}

// ---------------- launch -----------------------------------------------------
extern "C" void kernel_launch(void* const* d_in, const int* in_sizes, int n_in,
                              void* d_out, int out_size) {
    const float* x      = (const float*)d_in[0];
    const float* cond   = (const float*)d_in[1];
    const float* ln_g   = (const float*)d_in[2];
    const float* ln_b   = (const float*)d_in[3];
    const float* pre_w  = (const float*)d_in[4];
    const float* pre_b  = (const float*)d_in[5];
    const float* qkv_w  = (const float*)d_in[6];
    const float* mn_w   = (const float*)d_in[7];
    const float* gating = (const float*)d_in[8];
    const float* proj_w = (const float*)d_in[9];
    float* out = (float*)d_out;

    float *p_y, *p_v;
    cudaGetSymbolAddress((void**)&p_y, g_y);
    cudaGetSymbolAddress((void**)&p_v, g_v);

    const int SM1 = (C * AS + 16 * WS + 256 + 256 + 128 + 128) * 4;       // 120320
    const int SM2 = (C * AS + 16 * WS) * 4 + 2 * C * QS * 2;              // 221696
    const int SM4 = (C * AS + 16 * WS + NH * D * D) * 4;                  // 141824
    cudaFuncSetAttribute(k1_ln_pre, cudaFuncAttributeMaxDynamicSharedMemorySize, SM1);
    cudaFuncSetAttribute(k2_qkv,    cudaFuncAttributeMaxDynamicSharedMemorySize, SM2);
    cudaFuncSetAttribute(k4_final,  cudaFuncAttributeMaxDynamicSharedMemorySize, SM4);

    zero_kernel<<<1, 256>>>();
    k1_ln_pre<<<HW / TP, 256, SM1>>>(x, ln_g, ln_b, pre_w, pre_b, p_y);
    k2_qkv<<<HW / TP, 256, SM2>>>(p_y, qkv_w, p_v);
    gmk_kernel<<<1, 256>>>(mn_w, gating);
    k4_final<<<HW / TP, 256, SM4>>>(cond, x, proj_w, p_v, out);
}

// round 4
// speedup vs baseline: 4.9586x; 1.9777x over previous
#include <cuda_runtime.h>
#include <cuda_bf16.h>

#define HW 200704
#define C 192
#define TP 128
#define NH 6
#define D 32
#define PXS 100   // u32 stride for px-major bf16x2 tiles (96 ch-pairs + 4 pad)
#define WST 200   // u32 stride per k-pair row in weight chunk
#define QS  136   // bf16 stride for ch-major q/k tiles
#define MS  (96 * 192)   // u32 per converted weight matrix

// ---------------- scratch ----------------------------------------------------
__device__ unsigned g_wbf[5 * MS];                    // pre,q,k,v,proj bf16x2 [cp][o]
__device__ unsigned g_v[(size_t)(HW / TP) * TP * 96]; // v tiles, px-major bf16x2
__device__ float    g_G[NH * D * D];
__device__ float    g_qs2[C];
__device__ float    g_ks2[C];
__device__ unsigned g_gmbf[C * 16];                   // gm bf16x2 pairs [ch][e/2]

// ---------------- helpers ----------------------------------------------------
__device__ __forceinline__ unsigned packbf(float a, float b) {
    __nv_bfloat162 p = __floats2bfloat162_rn(a, b);
    return *(unsigned*)&p;
}
__device__ __forceinline__ float2 unpbf(unsigned u) {
    __nv_bfloat162 p = *(__nv_bfloat162*)&u;
    return __bfloat1622float2(p);
}
__device__ __forceinline__ void mma_bf16(float d[4], const unsigned a[4],
                                         unsigned b0, unsigned b1) {
    asm volatile(
        "mma.sync.aligned.m16n8k16.row.col.f32.bf16.bf16.f32 "
        "{%0,%1,%2,%3},{%4,%5,%6,%7},{%8,%9},{%0,%1,%2,%3};\n"
        : "+f"(d[0]), "+f"(d[1]), "+f"(d[2]), "+f"(d[3])
        : "r"(a[0]), "r"(a[1]), "r"(a[2]), "r"(a[3]), "r"(b0), "r"(b1));
}

// bf16 GEMM over a px-major [128px][96 cpair] smem tile (stride PXS u32) with a
// pre-converted weight matrix streamed through w_s in K=32 chunks.
// Warp grid 2Mx4N: warp tile 64px x 48out. All 256 threads must call.
__device__ __forceinline__ void gemm_bf(const unsigned* a_s, unsigned* w_s,
                                        const unsigned* __restrict__ wg,
                                        float acc[4][6][4], int tid) {
    const int lane = tid & 31, warp = tid >> 5;
    const int gid = lane >> 2, tg = lane & 3;
    const int mb = (warp & 1) * 64, nb = (warp >> 1) * 48;
    for (int ch = 0; ch < 6; ch++) {
        __syncthreads();
        for (int i = tid; i < 3072; i += 256) {
            int j = i / 192, o = i - j * 192;
            w_s[j * WST + o] = wg[ch * 3072 + i];
        }
        __syncthreads();
#pragma unroll
        for (int kl = 0; kl < 2; kl++) {
            const int k2 = ch * 16 + kl * 8;
            unsigned a[4][4];
#pragma unroll
            for (int mt = 0; mt < 4; mt++) {
                const unsigned* ab = a_s + (mb + mt * 16 + gid) * PXS + k2 + tg;
                a[mt][0] = ab[0];
                a[mt][1] = ab[8 * PXS];
                a[mt][2] = ab[4];
                a[mt][3] = ab[8 * PXS + 4];
            }
#pragma unroll
            for (int nt = 0; nt < 6; nt++) {
                const unsigned* wb = w_s + (kl * 8 + tg) * WST + nb + nt * 8 + gid;
                unsigned b0 = wb[0], b1 = wb[4 * WST];
#pragma unroll
                for (int mt = 0; mt < 4; mt++) mma_bf16(acc[mt][nt], a[mt], b0, b1);
            }
        }
    }
}

// ---------------- prep: convert weights to bf16x2 + zero accumulators --------
__global__ void prep_kernel(const float* __restrict__ pre_w,
                            const float* __restrict__ qkv_w,
                            const float* __restrict__ proj_w) {
    int idx = blockIdx.x * 256 + threadIdx.x;
    if (idx < 5 * MS) {
        int m = idx / MS, r = idx - m * MS;
        int cp = r / 192, o = r - cp * 192;
        const float* W = (m == 0) ? pre_w : (m < 4 ? qkv_w + (m - 1) * C * C : proj_w);
        g_wbf[idx] = packbf(W[o * C + 2 * cp], W[o * C + 2 * cp + 1]);
    }
    if (blockIdx.x == 0) {
        for (int i = threadIdx.x; i < NH * D * D; i += 256) g_G[i] = 0.f;
        if (threadIdx.x < C) {
            g_qs2[threadIdx.x] = 0.f;
            g_ks2[threadIdx.x] = 0.f;
        }
    }
}

// ---------------- k12: LN + pre + qkv + Gram ---------------------------------
__global__ __launch_bounds__(256, 1) void k12(const float* __restrict__ x,
                                              const float* __restrict__ lng,
                                              const float* __restrict__ lnb,
                                              const float* __restrict__ pre_b) {
    extern __shared__ unsigned sm[];
    unsigned* bufA = sm;                               // 13056 u32: x tile -> q_s
    unsigned* y_s  = sm + 13056;                       // 12800
    unsigned* kbuf = sm + 13056 + 12800;               // 13056: k_s
    unsigned* w_s  = sm + 13056 + 12800 + 13056;       // 3200
    float* gb = (float*)(w_s + 3200);                  // g[192], b[192]
    float* mu = gb + 384;                              // 128
    float* rs = mu + 128;                              // 128
    const int tid = threadIdx.x, lane = tid & 31, warp = tid >> 5;
    const int gid = lane >> 2, tg = lane & 3;
    const int mb = (warp & 1) * 64, nb = (warp >> 1) * 48;
    const int p0 = blockIdx.x * TP;

    for (int i = tid; i < C; i += 256) {
        gb[i]     = lng[i];
        gb[192 + i] = lnb[i];
    }
    // x transpose into px-major bf16x2
    for (int c2 = warp; c2 < 96; c2 += 8) {
        int c = 2 * c2;
#pragma unroll
        for (int pb = 0; pb < 128; pb += 32) {
            float v0 = x[(size_t)c * HW + p0 + pb + lane];
            float v1 = x[(size_t)(c + 1) * HW + p0 + pb + lane];
            bufA[(pb + lane) * PXS + c2] = packbf(v0, v1);
        }
    }
    __syncthreads();
    // LN stats: warp per 16 px rows, lanes over channel pairs, shuffle reduce
    for (int px = warp; px < 128; px += 8) {
        float s = 0.f, s2 = 0.f;
        for (int c2 = lane; c2 < 96; c2 += 32) {
            float2 f = unpbf(bufA[px * PXS + c2]);
            s += f.x + f.y;
            s2 += f.x * f.x + f.y * f.y;
        }
#pragma unroll
        for (int o = 16; o; o >>= 1) {
            s  += __shfl_xor_sync(~0u, s, o);
            s2 += __shfl_xor_sync(~0u, s2, o);
        }
        if (lane == 0) {
            float m = s * (1.f / C), v = s2 * (1.f / C) - m * m;
            mu[px] = m;
            rs[px] = rsqrtf(v + 1e-5f);
        }
    }
    __syncthreads();
    // apply LN
    for (int px = warp; px < 128; px += 8) {
        float m = mu[px], r = rs[px];
        for (int c2 = lane; c2 < 96; c2 += 32) {
            float2 f = unpbf(bufA[px * PXS + c2]);
            f.x = (f.x - m) * r * gb[2 * c2]     + gb[192 + 2 * c2];
            f.y = (f.y - m) * r * gb[2 * c2 + 1] + gb[192 + 2 * c2 + 1];
            bufA[px * PXS + c2] = packbf(f.x, f.y);
        }
    }

    float acc[4][6][4];
    // ---- pre GEMM (bias init) ----
#pragma unroll
    for (int nt = 0; nt < 6; nt++) {
        int o = nb + nt * 8 + 2 * tg;
        float b0 = __ldg(&pre_b[o]), b1 = __ldg(&pre_b[o + 1]);
#pragma unroll
        for (int mt = 0; mt < 4; mt++) {
            acc[mt][nt][0] = b0; acc[mt][nt][1] = b1;
            acc[mt][nt][2] = b0; acc[mt][nt][3] = b1;
        }
    }
    gemm_bf(bufA, w_s, g_wbf, acc, tid);
#pragma unroll
    for (int mt = 0; mt < 4; mt++)
#pragma unroll
        for (int nt = 0; nt < 6; nt++) {
            int px = mb + mt * 16 + gid, cp = (nb + nt * 8) / 2 + tg;
            y_s[px * PXS + cp]       = packbf(acc[mt][nt][0], acc[mt][nt][1]);
            y_s[(px + 8) * PXS + cp] = packbf(acc[mt][nt][2], acc[mt][nt][3]);
        }
    // ---- q GEMM ----
#pragma unroll
    for (int mt = 0; mt < 4; mt++)
#pragma unroll
        for (int nt = 0; nt < 6; nt++)
#pragma unroll
            for (int r = 0; r < 4; r++) acc[mt][nt][r] = 0.f;
    gemm_bf(y_s, w_s, g_wbf + MS, acc, tid);
    {
        __nv_bfloat16* q_s = (__nv_bfloat16*)bufA;
#pragma unroll
        for (int mt = 0; mt < 4; mt++)
#pragma unroll
            for (int nt = 0; nt < 6; nt++) {
                int o = nb + nt * 8 + 2 * tg, p = mb + mt * 16 + gid;
                q_s[o * QS + p]           = __float2bfloat16(acc[mt][nt][0]);
                q_s[(o + 1) * QS + p]     = __float2bfloat16(acc[mt][nt][1]);
                q_s[o * QS + p + 8]       = __float2bfloat16(acc[mt][nt][2]);
                q_s[(o + 1) * QS + p + 8] = __float2bfloat16(acc[mt][nt][3]);
            }
    }
    // ---- k GEMM ----
#pragma unroll
    for (int mt = 0; mt < 4; mt++)
#pragma unroll
        for (int nt = 0; nt < 6; nt++)
#pragma unroll
            for (int r = 0; r < 4; r++) acc[mt][nt][r] = 0.f;
    gemm_bf(y_s, w_s, g_wbf + 2 * MS, acc, tid);
    {
        __nv_bfloat16* k_s = (__nv_bfloat16*)kbuf;
#pragma unroll
        for (int mt = 0; mt < 4; mt++)
#pragma unroll
            for (int nt = 0; nt < 6; nt++) {
                int o = nb + nt * 8 + 2 * tg, p = mb + mt * 16 + gid;
                k_s[o * QS + p]           = __float2bfloat16(acc[mt][nt][0]);
                k_s[(o + 1) * QS + p]     = __float2bfloat16(acc[mt][nt][1]);
                k_s[o * QS + p + 8]       = __float2bfloat16(acc[mt][nt][2]);
                k_s[(o + 1) * QS + p + 8] = __float2bfloat16(acc[mt][nt][3]);
            }
    }
    // ---- v GEMM -> DRAM bf16x2 px-major ----
#pragma unroll
    for (int mt = 0; mt < 4; mt++)
#pragma unroll
        for (int nt = 0; nt < 6; nt++)
#pragma unroll
            for (int r = 0; r < 4; r++) acc[mt][nt][r] = 0.f;
    gemm_bf(y_s, w_s, g_wbf + 3 * MS, acc, tid);
    {
        unsigned* vt = g_v + (size_t)blockIdx.x * (TP * 96);
#pragma unroll
        for (int mt = 0; mt < 4; mt++)
#pragma unroll
            for (int nt = 0; nt < 6; nt++) {
                int px = mb + mt * 16 + gid, cp = (nb + nt * 8) / 2 + tg;
                vt[px * 96 + cp]       = packbf(acc[mt][nt][0], acc[mt][nt][1]);
                vt[(px + 8) * 96 + cp] = packbf(acc[mt][nt][2], acc[mt][nt][3]);
            }
    }
    __syncthreads();

    // ---- Gram per head via bf16 mma over 128 px (warp w == head w) ----
    if (warp < 6) {
        const __nv_bfloat16* q_s = (const __nv_bfloat16*)bufA;
        const __nv_bfloat16* k_s = (const __nv_bfloat16*)kbuf;
        const int h = warp;
        float dG[2][4][4];
#pragma unroll
        for (int mt = 0; mt < 2; mt++)
#pragma unroll
            for (int nt = 0; nt < 4; nt++)
#pragma unroll
                for (int r = 0; r < 4; r++) dG[mt][nt][r] = 0.f;
        for (int kc = 0; kc < TP; kc += 16) {
            unsigned a[2][4];
#pragma unroll
            for (int mt = 0; mt < 2; mt++) {
                const __nv_bfloat16* ab = q_s + (h * 32 + mt * 16 + gid) * QS + kc + 2 * tg;
                a[mt][0] = *(const unsigned*)(ab);
                a[mt][1] = *(const unsigned*)(ab + 8 * QS);
                a[mt][2] = *(const unsigned*)(ab + 8);
                a[mt][3] = *(const unsigned*)(ab + 8 * QS + 8);
            }
#pragma unroll
            for (int nt = 0; nt < 4; nt++) {
                const __nv_bfloat16* bb = k_s + (h * 32 + nt * 8 + gid) * QS + kc + 2 * tg;
                unsigned b0 = *(const unsigned*)(bb);
                unsigned b1 = *(const unsigned*)(bb + 8);
#pragma unroll
                for (int mt = 0; mt < 2; mt++) mma_bf16(dG[mt][nt], a[mt], b0, b1);
            }
        }
#pragma unroll
        for (int mt = 0; mt < 2; mt++)
#pragma unroll
            for (int nt = 0; nt < 4; nt++) {
                int r0 = h * 32 + mt * 16 + gid, c0 = nt * 8 + 2 * tg;
                atomicAdd(&g_G[r0 * 32 + c0],           dG[mt][nt][0]);
                atomicAdd(&g_G[r0 * 32 + c0 + 1],       dG[mt][nt][1]);
                atomicAdd(&g_G[(r0 + 8) * 32 + c0],     dG[mt][nt][2]);
                atomicAdd(&g_G[(r0 + 8) * 32 + c0 + 1], dG[mt][nt][3]);
            }
    }
    // squared norms from the same bf16 values
    for (int i = tid; i < 2 * C; i += 256) {
        const unsigned* arr = (i < C) ? bufA : kbuf;
        int row = (i < C) ? i : i - C;
        const unsigned* rp = arr + row * (QS / 2);
        float s = 0.f;
        for (int p = 0; p < 64; p++) {
            float2 f = unpbf(rp[p]);
            s += f.x * f.x + f.y * f.y;
        }
        atomicAdd((i < C) ? &g_qs2[row] : &g_ks2[row], s);
    }
}

// ---------------- gmk: attn normalize + mn mix + gating (12 blocks) ----------
__global__ void gmk_kernel(const float* __restrict__ mn_w,
                           const float* __restrict__ gating) {
    __shared__ float mn_t[32 * 64];  // [e][o]
    __shared__ float rk_s[32];
    const int tid = threadIdx.x;
    const int idx = blockIdx.x * 256 + tid;  // pair index
    const int dd = idx >> 4, pr = idx & 15, h = dd >> 5;
    for (int i = tid; i < 2048; i += 256) mn_t[(i & 31) * 64 + (i >> 5)] = mn_w[i];
    if (tid < 32) rk_s[tid] = 1.f / fmaxf(sqrtf(g_ks2[h * 32 + tid]), 1e-12f);
    __syncthreads();
    float rq = 1.f / fmaxf(sqrtf(g_qs2[dd]), 1e-12f);
    float a[32];
#pragma unroll
    for (int e = 0; e < 32; e++) a[e] = g_G[dd * 32 + e] * rq * rk_s[e];
    float s1a = 0.f, s1b = 0.f, s2a = 0.f, s2b = 0.f;
#pragma unroll
    for (int e = 0; e < 32; e++) {
        const float* mr = mn_t + e * 64;
        s1a += a[e] * mr[2 * pr];
        s1b += a[e] * mr[2 * pr + 1];
        s2a += a[e] * mr[32 + 2 * pr];
        s2b += a[e] * mr[33 + 2 * pr];
    }
    float g1 = __ldg(&gating[h]), g2 = __ldg(&gating[NH + h]);
    g_gmbf[idx] = packbf(g1 * s1a + g2 * s2a, g1 * s1b + g2 * s2b);
}

// ---------------- k4: mi(mma) + t=mi*v + softmax + proj(mma) + residual ------
__global__ __launch_bounds__(256, 1) void k4(const float* __restrict__ cond,
                                             const float* __restrict__ x,
                                             float* __restrict__ out) {
    extern __shared__ unsigned sm[];
    unsigned* c_s  = sm;                         // 12800 u32: cond -> softmax result
    float*    t_s  = (float*)(sm + 12800);       // 25600 f (stride 200)
    unsigned* w_s  = sm + 12800 + 25600;         // 3200
    unsigned* gm_s = sm + 12800 + 25600 + 3200;  // 192*20
    const int tid = threadIdx.x, lane = tid & 31, warp = tid >> 5;
    const int gid = lane >> 2, tg = lane & 3;
    const int mb = (warp & 1) * 64, nb = (warp >> 1) * 48;
    const int p0 = blockIdx.x * TP;

    for (int i = tid; i < C * 16; i += 256) gm_s[(i >> 4) * 20 + (i & 15)] = g_gmbf[i];
    for (int c2 = warp; c2 < 96; c2 += 8) {
        int c = 2 * c2;
#pragma unroll
        for (int pb = 0; pb < 128; pb += 32) {
            float v0 = cond[(size_t)c * HW + p0 + pb + lane];
            float v1 = cond[(size_t)(c + 1) * HW + p0 + pb + lane];
            c_s[(pb + lane) * PXS + c2] = packbf(v0, v1);
        }
    }
    __syncthreads();

    // mi[px][ch] = sum_e cond[px][h*32+e] * gm[ch][e]
    float acc[4][6][4];
#pragma unroll
    for (int mt = 0; mt < 4; mt++)
#pragma unroll
        for (int nt = 0; nt < 6; nt++)
#pragma unroll
            for (int r = 0; r < 4; r++) acc[mt][nt][r] = 0.f;
#pragma unroll
    for (int kl = 0; kl < 2; kl++) {
        const int k2 = kl * 8;
        int hprev = -1;
        unsigned a[4][4];
#pragma unroll
        for (int nt = 0; nt < 6; nt++) {
            int h = (nb + nt * 8) >> 5;
            if (h != hprev) {
#pragma unroll
                for (int mt = 0; mt < 4; mt++) {
                    const unsigned* ab = c_s + (mb + mt * 16 + gid) * PXS + h * 16 + k2 + tg;
                    a[mt][0] = ab[0];
                    a[mt][1] = ab[8 * PXS];
                    a[mt][2] = ab[4];
                    a[mt][3] = ab[8 * PXS + 4];
                }
                hprev = h;
            }
            const unsigned* gp = gm_s + (nb + nt * 8 + gid) * 20 + k2 + tg;
            unsigned b0 = gp[0], b1 = gp[4];
#pragma unroll
            for (int mt = 0; mt < 4; mt++) mma_bf16(acc[mt][nt], a[mt], b0, b1);
        }
    }

    // t = mi * v  -> t_s fp32 [px][ch] stride 200
    {
        const unsigned* vt = g_v + (size_t)blockIdx.x * (TP * 96);
#pragma unroll
        for (int mt = 0; mt < 4; mt++)
#pragma unroll
            for (int nt = 0; nt < 6; nt++) {
                int px = mb + mt * 16 + gid, cp = (nb + nt * 8) / 2 + tg;
                int chb = nb + nt * 8 + 2 * tg;
                float2 v0 = unpbf(__ldg(&vt[px * 96 + cp]));
                float2 v1 = unpbf(__ldg(&vt[(px + 8) * 96 + cp]));
                *(float2*)(t_s + px * 200 + chb) =
                    make_float2(acc[mt][nt][0] * v0.x, acc[mt][nt][1] * v0.y);
                *(float2*)(t_s + (px + 8) * 200 + chb) =
                    make_float2(acc[mt][nt][2] * v1.x, acc[mt][nt][3] * v1.y);
            }
    }
    __syncthreads();

    // softmax over head-dim (32 ch) per (px, head); write bf16x2 into c_s
#pragma unroll
    for (int k = 0; k < 3; k++) {
        int task = tid + k * 256;
        int px = task & 127, h = task >> 7;
        float* row = t_s + px * 200 + h * 32;
        float m = -1e30f;
#pragma unroll
        for (int d = 0; d < 32; d++) m = fmaxf(m, row[d]);
        float e[32], s = 0.f;
#pragma unroll
        for (int d = 0; d < 32; d++) {
            e[d] = __expf(row[d] - m);
            s += e[d];
        }
        float r = 1.f / s;
        unsigned* srow = c_s + px * PXS + h * 16;
#pragma unroll
        for (int j = 0; j < 16; j++) srow[j] = packbf(e[2 * j] * r, e[2 * j + 1] * r);
    }
    __syncthreads();

    // proj GEMM + residual
#pragma unroll
    for (int mt = 0; mt < 4; mt++)
#pragma unroll
        for (int nt = 0; nt < 6; nt++)
#pragma unroll
            for (int r = 0; r < 4; r++) acc[mt][nt][r] = 0.f;
    gemm_bf(c_s, w_s, g_wbf + 4 * MS, acc, tid);
#pragma unroll
    for (int mt = 0; mt < 4; mt++)
#pragma unroll
        for (int nt = 0; nt < 6; nt++) {
            int o = nb + nt * 8 + 2 * tg;
            size_t i00 = (size_t)o * HW + p0 + mb + mt * 16 + gid;
            out[i00]          = acc[mt][nt][0] + __ldg(&x[i00]);
            out[i00 + HW]     = acc[mt][nt][1] + __ldg(&x[i00 + HW]);
            out[i00 + 8]      = acc[mt][nt][2] + __ldg(&x[i00 + 8]);
            out[i00 + HW + 8] = acc[mt][nt][3] + __ldg(&x[i00 + HW + 8]);
        }
}

// ---------------- launch -----------------------------------------------------
extern "C" void kernel_launch(void* const* d_in, const int* in_sizes, int n_in,
                              void* d_out, int out_size) {
    const float* x      = (const float*)d_in[0];
    const float* cond   = (const float*)d_in[1];
    const float* ln_g   = (const float*)d_in[2];
    const float* ln_b   = (const float*)d_in[3];
    const float* pre_w  = (const float*)d_in[4];
    const float* pre_b  = (const float*)d_in[5];
    const float* qkv_w  = (const float*)d_in[6];
    const float* mn_w   = (const float*)d_in[7];
    const float* gating = (const float*)d_in[8];
    const float* proj_w = (const float*)d_in[9];
    float* out = (float*)d_out;

    const int SM12 = (13056 + 12800 + 13056 + 3200) * 4 + (384 + 128 + 128) * 4; // 171008
    const int SM4  = (12800 + 25600 + 3200 + 192 * 20) * 4;                      // 181760
    cudaFuncSetAttribute(k12, cudaFuncAttributeMaxDynamicSharedMemorySize, SM12);
    cudaFuncSetAttribute(k4,  cudaFuncAttributeMaxDynamicSharedMemorySize, SM4);

    prep_kernel<<<(5 * MS + 255) / 256, 256>>>(pre_w, qkv_w, proj_w);
    k12<<<HW / TP, 256, SM12>>>(x, ln_g, ln_b, pre_b);
    gmk_kernel<<<12, 256>>>(mn_w, gating);
    k4<<<HW / TP, 256, SM4>>>(cond, x, out);
}